// round 1
// baseline (speedup 1.0000x reference)
#include <cuda_runtime.h>

#define NN  131072
#define CC  128
#define SS  6
#define BB  6
#define EE  131072
#define ELE 32768
#define GN_EPS 1e-5f

// Scratch (device globals are the sanctioned no-alloc workaround)
static __device__ float g_bufA[(size_t)NN * CC];
static __device__ float g_bufB[(size_t)NN * CC];
static __device__ float g_temp[(size_t)NN * CC];
static __device__ float g_h[(size_t)NN * CC];

// ---------- packed f32x2 helpers ----------
__device__ __forceinline__ unsigned long long pk2(float a, float b) {
    unsigned long long r;
    asm("mov.b64 %0, {%1, %2};" : "=l"(r) : "f"(a), "f"(b));
    return r;
}
__device__ __forceinline__ void upk2(unsigned long long v, float& a, float& b) {
    asm("mov.b64 {%0, %1}, %2;" : "=f"(a), "=f"(b) : "l"(v));
}
__device__ __forceinline__ void fma2(unsigned long long& d, unsigned long long a, unsigned long long b) {
    asm("fma.rn.f32x2 %0, %1, %2, %0;" : "+l"(d) : "l"(a), "l"(b));
}

// ---------- fused gather-GEMM-scatter / dense GEMM ----------
// Tile: 128 rows (edges or nodes) x 128 cols. 256 threads, each thread 8 rows x 8 cols.
// W (128x128) fully resident in smem; A staged in k-chunks of 32.
// SCATTER=true : rows are edges; A rows gathered via v_idx, result atomically added at u_idx.
// SCATTER=false: rows are nodes row0+r; result stored (initializes temp).
#define SMEM_FLOATS (CC * CC + 128 * 33)
#define SMEM_BYTES  (SMEM_FLOATS * 4 + 256 * 4)

template <bool SCATTER>
__global__ void __launch_bounds__(256, 2)
msg_gemm_kernel(const float* __restrict__ X,
                const float* __restrict__ Wbase,   // + blockIdx.y * C*C
                const int* __restrict__ u_idx,     // + blockIdx.y * n_rows
                const int* __restrict__ v_idx,
                float* __restrict__ out,
                int n_rows)
{
    extern __shared__ float smem[];
    float* sW = smem;                    // [128][128]
    float* sA = smem + CC * CC;          // [128][33] padded
    int*   sU = (int*)(sA + 128 * 33);   // [128]
    int*   sV = sU + 128;                // [128]

    const int tid = threadIdx.x;
    const int tx  = tid & 15;            // col group: quads at 4*tx and 4*tx+64
    const int ty  = tid >> 4;            // row group: rows ty*8 .. ty*8+7

    // Load W for this weight index (blockIdx.y)
    {
        const float4* src = (const float4*)(Wbase + (size_t)blockIdx.y * CC * CC);
        float4* dst = (float4*)sW;
#pragma unroll
        for (int i = 0; i < 16; i++) dst[tid + 256 * i] = src[tid + 256 * i];
    }

    const int n_tiles = n_rows >> 7;
#pragma unroll 1
    for (int tile = blockIdx.x; tile < n_tiles; tile += gridDim.x) {
        const int row0 = tile << 7;
        __syncthreads();   // W ready (first iter) / guard sU,sV,sA overwrite
        if (SCATTER) {
            if (tid < 128) {
                size_t eb = (size_t)blockIdx.y * n_rows + row0 + tid;
                sU[tid] = u_idx[eb];
                sV[tid] = v_idx[eb];
            }
        }
        __syncthreads();

        unsigned long long acc[8][4];
#pragma unroll
        for (int r = 0; r < 8; r++)
#pragma unroll
            for (int q = 0; q < 4; q++) acc[r][q] = 0ull;

#pragma unroll 1
        for (int kc = 0; kc < 4; kc++) {
            if (kc) __syncthreads();
            // stage A chunk: 128 rows x 32 k (gathered if SCATTER)
#pragma unroll
            for (int j = 0; j < 4; j++) {
                int fi = tid + j * 256;      // 0..1023 float4 slots
                int r  = fi >> 3;
                int q  = fi & 7;
                int src_row = SCATTER ? sV[r] : (row0 + r);
                const float4 v = *(const float4*)(X + (size_t)src_row * CC + kc * 32 + q * 4);
                float* d = sA + r * 33 + q * 4;
                d[0] = v.x; d[1] = v.y; d[2] = v.z; d[3] = v.w;
            }
            __syncthreads();
#pragma unroll
            for (int kk = 0; kk < 32; kk++) {
                const float* wrow = sW + (kc * 32 + kk) * CC;
                const ulonglong2 w0 = *(const ulonglong2*)(wrow + 4 * tx);
                const ulonglong2 w1 = *(const ulonglong2*)(wrow + 4 * tx + 64);
#pragma unroll
                for (int r = 0; r < 8; r++) {
                    float a = sA[(ty * 8 + r) * 33 + kk];
                    unsigned long long a2 = pk2(a, a);
                    fma2(acc[r][0], a2, w0.x);
                    fma2(acc[r][1], a2, w0.y);
                    fma2(acc[r][2], a2, w1.x);
                    fma2(acc[r][3], a2, w1.y);
                }
            }
        }
        // epilogue
#pragma unroll
        for (int r = 0; r < 8; r++) {
            const int lrow = ty * 8 + r;
            float* base = SCATTER ? (out + (size_t)sU[lrow] * CC)
                                  : (out + (size_t)(row0 + lrow) * CC);
            if (SCATTER) {
                float v0, v1, v2, v3;
                upk2(acc[r][0], v0, v1); upk2(acc[r][1], v2, v3);
                atomicAdd(base + 4 * tx + 0, v0);
                atomicAdd(base + 4 * tx + 1, v1);
                atomicAdd(base + 4 * tx + 2, v2);
                atomicAdd(base + 4 * tx + 3, v3);
                upk2(acc[r][2], v0, v1); upk2(acc[r][3], v2, v3);
                atomicAdd(base + 4 * tx + 64, v0);
                atomicAdd(base + 4 * tx + 65, v1);
                atomicAdd(base + 4 * tx + 66, v2);
                atomicAdd(base + 4 * tx + 67, v3);
            } else {
                ulonglong2 s0; s0.x = acc[r][0]; s0.y = acc[r][1];
                ulonglong2 s1; s1.x = acc[r][2]; s1.y = acc[r][3];
                *(ulonglong2*)(base + 4 * tx)      = s0;
                *(ulonglong2*)(base + 4 * tx + 64) = s1;
            }
        }
    }
}

// ---------- input encoder: Linear(2,C)+ReLU -> Linear(C,C) -> GN, twice, relu(sum) ----------
__global__ void encoder_kernel(const float* __restrict__ ctrs, const float* __restrict__ feats,
                               const float* __restrict__ icw0, const float* __restrict__ icb0,
                               const float* __restrict__ icw1, const float* __restrict__ icg,
                               const float* __restrict__ icbt,
                               const float* __restrict__ ifw0, const float* __restrict__ ifb0,
                               const float* __restrict__ ifw1, const float* __restrict__ ifg,
                               const float* __restrict__ ifbt,
                               float* __restrict__ out)
{
    const int tid = threadIdx.x;
    const int r = tid >> 7;
    const int c = tid & 127;
    const int row = (blockIdx.x << 1) + r;
    const int warp = (tid >> 5) & 3;
    const int lane = tid & 31;
    __shared__ float sh[2][CC];
    __shared__ float sred[2][2][4];

    float ysum = 0.f;
#pragma unroll
    for (int br = 0; br < 2; br++) {
        const float* x  = br ? feats : ctrs;
        const float* w0 = br ? ifw0 : icw0;
        const float* b0 = br ? ifb0 : icb0;
        const float* w1 = br ? ifw1 : icw1;
        const float* g  = br ? ifg  : icg;
        const float* bt = br ? ifbt : icbt;
        const float x0 = x[row * 2 + 0];
        const float x1 = x[row * 2 + 1];
        float h = fmaxf(fmaf(x1, w0[CC + c], fmaf(x0, w0[c], b0[c])), 0.f);
        __syncthreads();
        sh[r][c] = h;
        __syncthreads();
        float z = 0.f;
#pragma unroll 8
        for (int k = 0; k < CC; k++) z = fmaf(sh[r][k], w1[k * CC + c], z);
        float s = z, sq = z * z;
#pragma unroll
        for (int o = 16; o > 0; o >>= 1) {
            s  += __shfl_xor_sync(0xffffffffu, s, o);
            sq += __shfl_xor_sync(0xffffffffu, sq, o);
        }
        if (lane == 0) { sred[r][0][warp] = s; sred[r][1][warp] = sq; }
        __syncthreads();
        float mu  = (sred[r][0][0] + sred[r][0][1] + sred[r][0][2] + sred[r][0][3]) * (1.f / CC);
        float ms  = (sred[r][1][0] + sred[r][1][1] + sred[r][1][2] + sred[r][1][3]) * (1.f / CC);
        float var = ms - mu * mu;
        ysum += (z - mu) * rsqrtf(var + GN_EPS) * g[c] + bt[c];
    }
    out[(size_t)row * CC + c] = fmaxf(ysum, 0.f);
}

// ---------- GN + relu ----------
__global__ void norm_relu_kernel(const float* __restrict__ in,
                                 const float* __restrict__ g, const float* __restrict__ b,
                                 float* __restrict__ out)
{
    const int tid = threadIdx.x;
    const int r = tid >> 7, c = tid & 127;
    const size_t row = (size_t)(blockIdx.x << 1) + r;
    const int warp = (tid >> 5) & 3, lane = tid & 31;
    __shared__ float sred[2][2][4];
    float z = in[row * CC + c];
    float s = z, sq = z * z;
#pragma unroll
    for (int o = 16; o > 0; o >>= 1) {
        s  += __shfl_xor_sync(0xffffffffu, s, o);
        sq += __shfl_xor_sync(0xffffffffu, sq, o);
    }
    if (lane == 0) { sred[r][0][warp] = s; sred[r][1][warp] = sq; }
    __syncthreads();
    float mu  = (sred[r][0][0] + sred[r][0][1] + sred[r][0][2] + sred[r][0][3]) * (1.f / CC);
    float ms  = (sred[r][1][0] + sred[r][1][1] + sred[r][1][2] + sred[r][1][3]) * (1.f / CC);
    float var = ms - mu * mu;
    float y = (z - mu) * rsqrtf(var + GN_EPS) * g[c] + b[c];
    out[row * CC + c] = fmaxf(y, 0.f);
}

// ---------- GN + residual add + relu ----------
__global__ void norm_res_kernel(const float* __restrict__ in,
                                const float* __restrict__ g, const float* __restrict__ b,
                                const float* __restrict__ iden, float* __restrict__ out)
{
    const int tid = threadIdx.x;
    const int r = tid >> 7, c = tid & 127;
    const size_t row = (size_t)(blockIdx.x << 1) + r;
    const int warp = (tid >> 5) & 3, lane = tid & 31;
    __shared__ float sred[2][2][4];
    float z = in[row * CC + c];
    float s = z, sq = z * z;
#pragma unroll
    for (int o = 16; o > 0; o >>= 1) {
        s  += __shfl_xor_sync(0xffffffffu, s, o);
        sq += __shfl_xor_sync(0xffffffffu, sq, o);
    }
    if (lane == 0) { sred[r][0][warp] = s; sred[r][1][warp] = sq; }
    __syncthreads();
    float mu  = (sred[r][0][0] + sred[r][0][1] + sred[r][0][2] + sred[r][0][3]) * (1.f / CC);
    float ms  = (sred[r][1][0] + sred[r][1][1] + sred[r][1][2] + sred[r][1][3]) * (1.f / CC);
    float var = ms - mu * mu;
    float y = (z - mu) * rsqrtf(var + GN_EPS) * g[c] + b[c];
    out[row * CC + c] = fmaxf(y + iden[row * CC + c], 0.f);
}

extern "C" void kernel_launch(void* const* d_in, const int* in_sizes, int n_in,
                              void* d_out, int out_size)
{
    const float* ctrs    = (const float*)d_in[0];
    const float* feats   = (const float*)d_in[1];
    const int*   pre_u   = (const int*)d_in[2];
    const int*   pre_v   = (const int*)d_in[3];
    const int*   suc_u   = (const int*)d_in[4];
    const int*   suc_v   = (const int*)d_in[5];
    const int*   left_u  = (const int*)d_in[6];
    const int*   left_v  = (const int*)d_in[7];
    const int*   right_u = (const int*)d_in[8];
    const int*   right_v = (const int*)d_in[9];
    const float* ic_w0   = (const float*)d_in[10];
    const float* ic_b0   = (const float*)d_in[11];
    const float* ic_w1   = (const float*)d_in[12];
    const float* ic_g    = (const float*)d_in[13];
    const float* ic_bt   = (const float*)d_in[14];
    const float* if_w0   = (const float*)d_in[15];
    const float* if_b0   = (const float*)d_in[16];
    const float* if_w1   = (const float*)d_in[17];
    const float* if_g    = (const float*)d_in[18];
    const float* if_bt   = (const float*)d_in[19];
    const float* ctr_w   = (const float*)d_in[20];
    const float* pre_w   = (const float*)d_in[21];
    const float* suc_w   = (const float*)d_in[22];
    const float* left_w  = (const float*)d_in[23];
    const float* right_w = (const float*)d_in[24];
    const float* norm_g  = (const float*)d_in[25];
    const float* norm_b  = (const float*)d_in[26];
    const float* ctr2_w  = (const float*)d_in[27];
    const float* ctr2_g  = (const float*)d_in[28];
    const float* ctr2_b  = (const float*)d_in[29];

    float *bufA, *bufB, *temp, *hbuf;
    cudaGetSymbolAddress((void**)&bufA, g_bufA);
    cudaGetSymbolAddress((void**)&bufB, g_bufB);
    cudaGetSymbolAddress((void**)&temp, g_temp);
    cudaGetSymbolAddress((void**)&hbuf, g_h);

    cudaFuncSetAttribute(msg_gemm_kernel<false>, cudaFuncAttributeMaxDynamicSharedMemorySize, SMEM_BYTES);
    cudaFuncSetAttribute(msg_gemm_kernel<true>,  cudaFuncAttributeMaxDynamicSharedMemorySize, SMEM_BYTES);

    // initial feat -> bufA
    encoder_kernel<<<NN / 2, 256>>>(ctrs, feats,
                                    ic_w0, ic_b0, ic_w1, ic_g, ic_bt,
                                    if_w0, if_b0, if_w1, if_g, if_bt, bufA);

    float* fin = bufA;   // feat == identity at block entry
    for (int i = 0; i < BB; i++) {
        // temp = feat @ ctr_w[i]   (dense write, initializes temp)
        msg_gemm_kernel<false><<<512, 256, SMEM_BYTES>>>(
            fin, ctr_w + (size_t)i * CC * CC, nullptr, nullptr, temp, NN);
        // scatter-add message passes
        msg_gemm_kernel<true><<<dim3(256, SS), 256, SMEM_BYTES>>>(
            fin, pre_w + (size_t)i * SS * CC * CC, pre_u, pre_v, temp, EE);
        msg_gemm_kernel<true><<<dim3(256, SS), 256, SMEM_BYTES>>>(
            fin, suc_w + (size_t)i * SS * CC * CC, suc_u, suc_v, temp, EE);
        msg_gemm_kernel<true><<<dim3(256, 1), 256, SMEM_BYTES>>>(
            fin, left_w + (size_t)i * CC * CC, left_u, left_v, temp, ELE);
        msg_gemm_kernel<true><<<dim3(256, 1), 256, SMEM_BYTES>>>(
            fin, right_w + (size_t)i * CC * CC, right_u, right_v, temp, ELE);
        // h = relu(GN(temp))
        norm_relu_kernel<<<NN / 2, 256>>>(temp, norm_g + i * CC, norm_b + i * CC, hbuf);
        // temp = h @ ctr2_w[i]
        msg_gemm_kernel<false><<<512, 256, SMEM_BYTES>>>(
            hbuf, ctr2_w + (size_t)i * CC * CC, nullptr, nullptr, temp, NN);
        // feat = relu(GN(temp) + identity)
        float* dst = (i == BB - 1) ? (float*)d_out : ((fin == bufA) ? bufB : bufA);
        norm_res_kernel<<<NN / 2, 256>>>(temp, ctr2_g + i * CC, ctr2_b + i * CC, fin, dst);
        fin = dst;
    }
}

// round 2
// speedup vs baseline: 1.6445x; 1.6445x over previous
#include <cuda_runtime.h>
#include <cuda_bf16.h>

#define NN  131072
#define CC  128
#define SS  6
#define BB  6
#define EE  131072
#define ELE 32768
#define GN_EPS 1e-5f

// Scratch (device globals are the sanctioned no-alloc workaround)
static __device__ float g_bufA[(size_t)NN * CC];
static __device__ float g_bufB[(size_t)NN * CC];
static __device__ float g_temp[(size_t)NN * CC];
static __device__ float g_h[(size_t)NN * CC];

// ---------------- bf16 pair-split helpers ----------------
__device__ __forceinline__ unsigned pack_bf2(__nv_bfloat16 lo16, __nv_bfloat16 hi16) {
    // lo16 goes to low 16 bits (even-k element), hi16 to high 16 bits (odd-k)
    __nv_bfloat162 t(lo16, hi16);
    return *reinterpret_cast<unsigned*>(&t);
}
__device__ __forceinline__ void bsplit(float x, __nv_bfloat16& h, __nv_bfloat16& l) {
    h = __float2bfloat16(x);
    l = __float2bfloat16(x - __bfloat162float(h));
}

__device__ __forceinline__ void mma16816(float acc[4],
                                         unsigned a0, unsigned a1, unsigned a2, unsigned a3,
                                         unsigned b0, unsigned b1) {
    asm volatile(
        "mma.sync.aligned.m16n8k16.row.col.f32.bf16.bf16.f32 "
        "{%0,%1,%2,%3}, {%4,%5,%6,%7}, {%8,%9}, {%0,%1,%2,%3};"
        : "+f"(acc[0]), "+f"(acc[1]), "+f"(acc[2]), "+f"(acc[3])
        : "r"(a0), "r"(a1), "r"(a2), "r"(a3), "r"(b0), "r"(b1));
}

// ---------------- fused gather-MMA-scatter / dense GEMM ----------------
// Tile: 128 rows x 128 cols, K=128. 256 threads = 8 warps (4 row groups x 2 col groups).
// W split hi/lo bf16, pair-packed along k: sW[n][kp], stride 68 (conflict-free frags).
// A gathered + split per 64-k chunk: sA[row][kp], stride 36.
// Accuracy: x*y ~= hh + h*lo + lo*h  (2-way bf16 split, ~2^-18 error)
#define WS 68
#define AS 36
#define SMEM_U32 (2 * (128 * WS) + 2 * (128 * AS) + 256)
#define SMEM_BYTES (SMEM_U32 * 4)

template <bool SCATTER>
__global__ void __launch_bounds__(256, 2)
msg_mma_kernel(const float* __restrict__ X,
               const float* __restrict__ Wbase,   // + blockIdx.y * C*C
               const int* __restrict__ u_idx,     // + blockIdx.y * n_rows
               const int* __restrict__ v_idx,
               float* __restrict__ out,
               int n_rows)
{
    extern __shared__ unsigned smem_u[];
    unsigned* sWhi = smem_u;                 // [128][WS]
    unsigned* sWlo = sWhi + 128 * WS;
    unsigned* sAhi = sWlo + 128 * WS;        // [128][AS]
    unsigned* sAlo = sAhi + 128 * AS;
    int* sU = (int*)(sAlo + 128 * AS);       // [128]
    int* sV = sU + 128;                      // [128]

    const int tid  = threadIdx.x;
    const int wid  = tid >> 5;
    const int lane = tid & 31;
    const int gid  = lane >> 2;              // group id 0..7
    const int tig  = lane & 3;               // thread in group
    const int wr   = wid & 3;                // row group: rows wr*32 .. +31
    const int wc   = wid >> 2;               // col group: cols wc*64 .. +63

    // ---- load W, split hi/lo, pack k-pairs into [n][kp] ----
    {
        const float* W = Wbase + (size_t)blockIdx.y * CC * CC;
#pragma unroll
        for (int i = 0; i < 32; i++) {
            int p  = tid + i * 256;          // pair index over (kp, n)
            int kp = p >> 7;
            int n  = p & 127;
            float w0 = W[(2 * kp) * CC + n];
            float w1 = W[(2 * kp + 1) * CC + n];
            __nv_bfloat16 h0, l0, h1, l1;
            bsplit(w0, h0, l0);
            bsplit(w1, h1, l1);
            sWhi[n * WS + kp] = pack_bf2(h0, h1);
            sWlo[n * WS + kp] = pack_bf2(l0, l1);
        }
    }

    const int row0 = blockIdx.x << 7;
    if (SCATTER) {
        if (tid < 128) {
            size_t eb = (size_t)blockIdx.y * n_rows + row0 + tid;
            sU[tid] = u_idx[eb];
            sV[tid] = v_idx[eb];
        }
    }
    __syncthreads();

    float acc[2][8][4];
#pragma unroll
    for (int rt = 0; rt < 2; rt++)
#pragma unroll
        for (int nt = 0; nt < 8; nt++)
#pragma unroll
            for (int q = 0; q < 4; q++) acc[rt][nt][q] = 0.f;

#pragma unroll 1
    for (int kc = 0; kc < 2; kc++) {
        if (kc) __syncthreads();
        // ---- stage A chunk: 128 rows x 64 k, gathered if SCATTER, split hi/lo ----
#pragma unroll
        for (int j = 0; j < 8; j++) {
            int fi = tid + j * 256;          // 0..2047 float4 slots
            int r  = fi >> 4;
            int q  = fi & 15;
            int src_row = SCATTER ? sV[r] : (row0 + r);
            const float4 v = *(const float4*)(X + (size_t)src_row * CC + kc * 64 + q * 4);
            __nv_bfloat16 h0, l0, h1, l1, h2, l2, h3, l3;
            bsplit(v.x, h0, l0); bsplit(v.y, h1, l1);
            bsplit(v.z, h2, l2); bsplit(v.w, h3, l3);
            sAhi[r * AS + 2 * q]     = pack_bf2(h0, h1);
            sAhi[r * AS + 2 * q + 1] = pack_bf2(h2, h3);
            sAlo[r * AS + 2 * q]     = pack_bf2(l0, l1);
            sAlo[r * AS + 2 * q + 1] = pack_bf2(l2, l3);
        }
        __syncthreads();

#pragma unroll
        for (int ks = 0; ks < 4; ks++) {     // four k16 steps per chunk
            const int kp0 = ks * 8;          // chunk-local pair base
            unsigned ah[2][4], al[2][4];
#pragma unroll
            for (int rt = 0; rt < 2; rt++) {
                const int ar = wr * 32 + rt * 16;
                ah[rt][0] = sAhi[(ar + gid) * AS + kp0 + tig];
                ah[rt][1] = sAhi[(ar + 8 + gid) * AS + kp0 + tig];
                ah[rt][2] = sAhi[(ar + gid) * AS + kp0 + 4 + tig];
                ah[rt][3] = sAhi[(ar + 8 + gid) * AS + kp0 + 4 + tig];
                al[rt][0] = sAlo[(ar + gid) * AS + kp0 + tig];
                al[rt][1] = sAlo[(ar + 8 + gid) * AS + kp0 + tig];
                al[rt][2] = sAlo[(ar + gid) * AS + kp0 + 4 + tig];
                al[rt][3] = sAlo[(ar + 8 + gid) * AS + kp0 + 4 + tig];
            }
#pragma unroll
            for (int nt = 0; nt < 8; nt++) {
                const int col = wc * 64 + nt * 8 + gid;
                const int kpg = kc * 32 + kp0;       // global pair base
                unsigned bh0 = sWhi[col * WS + kpg + tig];
                unsigned bh1 = sWhi[col * WS + kpg + 4 + tig];
                unsigned bl0 = sWlo[col * WS + kpg + tig];
                unsigned bl1 = sWlo[col * WS + kpg + 4 + tig];
#pragma unroll
                for (int rt = 0; rt < 2; rt++) {
                    mma16816(acc[rt][nt], ah[rt][0], ah[rt][1], ah[rt][2], ah[rt][3], bh0, bh1);
                    mma16816(acc[rt][nt], ah[rt][0], ah[rt][1], ah[rt][2], ah[rt][3], bl0, bl1);
                    mma16816(acc[rt][nt], al[rt][0], al[rt][1], al[rt][2], al[rt][3], bh0, bh1);
                }
            }
        }
    }

    // ---- epilogue: shfl-assemble float4 runs; red.v4 scatter or STG.128 ----
    const bool even = (tig & 1) == 0;
    const int colofs = (tig & 2) ? 4 : 0;
#pragma unroll
    for (int rt = 0; rt < 2; rt++) {
        const int arow = wr * 32 + rt * 16 + gid + (even ? 0 : 8);
        float* base;
        if (SCATTER) base = out + (size_t)sU[arow] * CC;
        else         base = out + (size_t)(row0 + arow) * CC;
#pragma unroll
        for (int nt = 0; nt < 8; nt++) {
            float c0 = acc[rt][nt][0], c1 = acc[rt][nt][1];
            float c2 = acc[rt][nt][2], c3 = acc[rt][nt][3];
            float e0 = __shfl_xor_sync(0xffffffffu, c0, 1);
            float e1 = __shfl_xor_sync(0xffffffffu, c1, 1);
            float e2 = __shfl_xor_sync(0xffffffffu, c2, 1);
            float e3 = __shfl_xor_sync(0xffffffffu, c3, 1);
            float x0, x1, x2, x3;
            int cb;
            if (even) { x0 = c0; x1 = c1; x2 = e0; x3 = e1; cb = wc * 64 + nt * 8 + colofs; }
            else      { x0 = e2; x1 = e3; x2 = c2; x3 = c3; cb = wc * 64 + nt * 8 + colofs; }
            float* p = base + cb;
            if (SCATTER) {
                asm volatile("red.global.add.v4.f32 [%0], {%1,%2,%3,%4};"
                             :: "l"(p), "f"(x0), "f"(x1), "f"(x2), "f"(x3) : "memory");
            } else {
                float4 v; v.x = x0; v.y = x1; v.z = x2; v.w = x3;
                *(float4*)p = v;
            }
        }
    }
}

// ---------- input encoder: Linear(2,C)+ReLU -> Linear(C,C) -> GN, twice, relu(sum) ----------
__global__ void encoder_kernel(const float* __restrict__ ctrs, const float* __restrict__ feats,
                               const float* __restrict__ icw0, const float* __restrict__ icb0,
                               const float* __restrict__ icw1, const float* __restrict__ icg,
                               const float* __restrict__ icbt,
                               const float* __restrict__ ifw0, const float* __restrict__ ifb0,
                               const float* __restrict__ ifw1, const float* __restrict__ ifg,
                               const float* __restrict__ ifbt,
                               float* __restrict__ out)
{
    const int tid = threadIdx.x;
    const int r = tid >> 7;
    const int c = tid & 127;
    const int row = (blockIdx.x << 1) + r;
    const int warp = (tid >> 5) & 3;
    const int lane = tid & 31;
    __shared__ float sh[2][CC];
    __shared__ float sred[2][2][4];

    float ysum = 0.f;
#pragma unroll
    for (int br = 0; br < 2; br++) {
        const float* x  = br ? feats : ctrs;
        const float* w0 = br ? ifw0 : icw0;
        const float* b0 = br ? ifb0 : icb0;
        const float* w1 = br ? ifw1 : icw1;
        const float* g  = br ? ifg  : icg;
        const float* bt = br ? ifbt : icbt;
        const float x0 = x[row * 2 + 0];
        const float x1 = x[row * 2 + 1];
        float h = fmaxf(fmaf(x1, w0[CC + c], fmaf(x0, w0[c], b0[c])), 0.f);
        __syncthreads();
        sh[r][c] = h;
        __syncthreads();
        float z = 0.f;
#pragma unroll 8
        for (int k = 0; k < CC; k++) z = fmaf(sh[r][k], w1[k * CC + c], z);
        float s = z, sq = z * z;
#pragma unroll
        for (int o = 16; o > 0; o >>= 1) {
            s  += __shfl_xor_sync(0xffffffffu, s, o);
            sq += __shfl_xor_sync(0xffffffffu, sq, o);
        }
        if (lane == 0) { sred[r][0][warp] = s; sred[r][1][warp] = sq; }
        __syncthreads();
        float mu  = (sred[r][0][0] + sred[r][0][1] + sred[r][0][2] + sred[r][0][3]) * (1.f / CC);
        float ms  = (sred[r][1][0] + sred[r][1][1] + sred[r][1][2] + sred[r][1][3]) * (1.f / CC);
        float var = ms - mu * mu;
        ysum += (z - mu) * rsqrtf(var + GN_EPS) * g[c] + bt[c];
    }
    out[(size_t)row * CC + c] = fmaxf(ysum, 0.f);
}

// ---------- GN + relu ----------
__global__ void norm_relu_kernel(const float* __restrict__ in,
                                 const float* __restrict__ g, const float* __restrict__ b,
                                 float* __restrict__ out)
{
    const int tid = threadIdx.x;
    const int r = tid >> 7, c = tid & 127;
    const size_t row = (size_t)(blockIdx.x << 1) + r;
    const int warp = (tid >> 5) & 3, lane = tid & 31;
    __shared__ float sred[2][2][4];
    float z = in[row * CC + c];
    float s = z, sq = z * z;
#pragma unroll
    for (int o = 16; o > 0; o >>= 1) {
        s  += __shfl_xor_sync(0xffffffffu, s, o);
        sq += __shfl_xor_sync(0xffffffffu, sq, o);
    }
    if (lane == 0) { sred[r][0][warp] = s; sred[r][1][warp] = sq; }
    __syncthreads();
    float mu  = (sred[r][0][0] + sred[r][0][1] + sred[r][0][2] + sred[r][0][3]) * (1.f / CC);
    float ms  = (sred[r][1][0] + sred[r][1][1] + sred[r][1][2] + sred[r][1][3]) * (1.f / CC);
    float var = ms - mu * mu;
    float y = (z - mu) * rsqrtf(var + GN_EPS) * g[c] + b[c];
    out[row * CC + c] = fmaxf(y, 0.f);
}

// ---------- GN + residual add + relu ----------
__global__ void norm_res_kernel(const float* __restrict__ in,
                                const float* __restrict__ g, const float* __restrict__ b,
                                const float* __restrict__ iden, float* __restrict__ out)
{
    const int tid = threadIdx.x;
    const int r = tid >> 7, c = tid & 127;
    const size_t row = (size_t)(blockIdx.x << 1) + r;
    const int warp = (tid >> 5) & 3, lane = tid & 31;
    __shared__ float sred[2][2][4];
    float z = in[row * CC + c];
    float s = z, sq = z * z;
#pragma unroll
    for (int o = 16; o > 0; o >>= 1) {
        s  += __shfl_xor_sync(0xffffffffu, s, o);
        sq += __shfl_xor_sync(0xffffffffu, sq, o);
    }
    if (lane == 0) { sred[r][0][warp] = s; sred[r][1][warp] = sq; }
    __syncthreads();
    float mu  = (sred[r][0][0] + sred[r][0][1] + sred[r][0][2] + sred[r][0][3]) * (1.f / CC);
    float ms  = (sred[r][1][0] + sred[r][1][1] + sred[r][1][2] + sred[r][1][3]) * (1.f / CC);
    float var = ms - mu * mu;
    float y = (z - mu) * rsqrtf(var + GN_EPS) * g[c] + b[c];
    out[row * CC + c] = fmaxf(y + iden[row * CC + c], 0.f);
}

extern "C" void kernel_launch(void* const* d_in, const int* in_sizes, int n_in,
                              void* d_out, int out_size)
{
    const float* ctrs    = (const float*)d_in[0];
    const float* feats   = (const float*)d_in[1];
    const int*   pre_u   = (const int*)d_in[2];
    const int*   pre_v   = (const int*)d_in[3];
    const int*   suc_u   = (const int*)d_in[4];
    const int*   suc_v   = (const int*)d_in[5];
    const int*   left_u  = (const int*)d_in[6];
    const int*   left_v  = (const int*)d_in[7];
    const int*   right_u = (const int*)d_in[8];
    const int*   right_v = (const int*)d_in[9];
    const float* ic_w0   = (const float*)d_in[10];
    const float* ic_b0   = (const float*)d_in[11];
    const float* ic_w1   = (const float*)d_in[12];
    const float* ic_g    = (const float*)d_in[13];
    const float* ic_bt   = (const float*)d_in[14];
    const float* if_w0   = (const float*)d_in[15];
    const float* if_b0   = (const float*)d_in[16];
    const float* if_w1   = (const float*)d_in[17];
    const float* if_g    = (const float*)d_in[18];
    const float* if_bt   = (const float*)d_in[19];
    const float* ctr_w   = (const float*)d_in[20];
    const float* pre_w   = (const float*)d_in[21];
    const float* suc_w   = (const float*)d_in[22];
    const float* left_w  = (const float*)d_in[23];
    const float* right_w = (const float*)d_in[24];
    const float* norm_g  = (const float*)d_in[25];
    const float* norm_b  = (const float*)d_in[26];
    const float* ctr2_w  = (const float*)d_in[27];
    const float* ctr2_g  = (const float*)d_in[28];
    const float* ctr2_b  = (const float*)d_in[29];

    float *bufA, *bufB, *temp, *hbuf;
    cudaGetSymbolAddress((void**)&bufA, g_bufA);
    cudaGetSymbolAddress((void**)&bufB, g_bufB);
    cudaGetSymbolAddress((void**)&temp, g_temp);
    cudaGetSymbolAddress((void**)&hbuf, g_h);

    cudaFuncSetAttribute(msg_mma_kernel<false>, cudaFuncAttributeMaxDynamicSharedMemorySize, SMEM_BYTES);
    cudaFuncSetAttribute(msg_mma_kernel<true>,  cudaFuncAttributeMaxDynamicSharedMemorySize, SMEM_BYTES);

    // initial feat -> bufA
    encoder_kernel<<<NN / 2, 256>>>(ctrs, feats,
                                    ic_w0, ic_b0, ic_w1, ic_g, ic_bt,
                                    if_w0, if_b0, if_w1, if_g, if_bt, bufA);

    float* fin = bufA;   // feat == identity at block entry
    for (int i = 0; i < BB; i++) {
        // temp = feat @ ctr_w[i]   (dense write, initializes temp)
        msg_mma_kernel<false><<<dim3(NN / 128, 1), 256, SMEM_BYTES>>>(
            fin, ctr_w + (size_t)i * CC * CC, nullptr, nullptr, temp, NN);
        // scatter-add message passes
        msg_mma_kernel<true><<<dim3(EE / 128, SS), 256, SMEM_BYTES>>>(
            fin, pre_w + (size_t)i * SS * CC * CC, pre_u, pre_v, temp, EE);
        msg_mma_kernel<true><<<dim3(EE / 128, SS), 256, SMEM_BYTES>>>(
            fin, suc_w + (size_t)i * SS * CC * CC, suc_u, suc_v, temp, EE);
        msg_mma_kernel<true><<<dim3(ELE / 128, 1), 256, SMEM_BYTES>>>(
            fin, left_w + (size_t)i * CC * CC, left_u, left_v, temp, ELE);
        msg_mma_kernel<true><<<dim3(ELE / 128, 1), 256, SMEM_BYTES>>>(
            fin, right_w + (size_t)i * CC * CC, right_u, right_v, temp, ELE);
        // h = relu(GN(temp))
        norm_relu_kernel<<<NN / 2, 256>>>(temp, norm_g + i * CC, norm_b + i * CC, hbuf);
        // temp = h @ ctr2_w[i]
        msg_mma_kernel<false><<<dim3(NN / 128, 1), 256, SMEM_BYTES>>>(
            hbuf, ctr2_w + (size_t)i * CC * CC, nullptr, nullptr, temp, NN);
        // feat = relu(GN(temp) + identity)
        float* dst = (i == BB - 1) ? (float*)d_out : ((fin == bufA) ? bufB : bufA);
        norm_res_kernel<<<NN / 2, 256>>>(temp, ctr2_g + i * CC, ctr2_b + i * CC, fin, dst);
        fin = dst;
    }
}

// round 3
// speedup vs baseline: 1.8563x; 1.1288x over previous
#include <cuda_runtime.h>
#include <cuda_bf16.h>

#define NN  131072
#define CC  128
#define SS  6
#define BB  6
#define EE  131072
#define ELE 32768
#define GN_EPS 1e-5f

// ---------------- device scratch ----------------
static __device__ float g_bufA[(size_t)NN * CC];
static __device__ float g_bufB[(size_t)NN * CC];
static __device__ float g_temp[(size_t)NN * CC];
// split planes: [N][64] u32 (bf16x2 pairs), hi then lo
static __device__ unsigned g_fhi[(size_t)NN * 64];
static __device__ unsigned g_flo[(size_t)NN * 64];
static __device__ unsigned g_hhi[(size_t)NN * 64];
static __device__ unsigned g_hlo[(size_t)NN * 64];
// split weights: [96][hi 8192 | lo 8192] u32, layout [n=128][kp=64]
static __device__ unsigned g_wsp[(size_t)96 * 16384];

// ---------------- bf16 split helpers ----------------
__device__ __forceinline__ unsigned pack_bf2(__nv_bfloat16 lo16, __nv_bfloat16 hi16) {
    __nv_bfloat162 t(lo16, hi16);
    return *reinterpret_cast<unsigned*>(&t);
}
__device__ __forceinline__ void bsplit(float x, __nv_bfloat16& h, __nv_bfloat16& l) {
    h = __float2bfloat16(x);
    l = __float2bfloat16(x - __bfloat162float(h));
}
// split two floats (even k = a, odd k = b) into packed hi/lo u32
__device__ __forceinline__ void split2(float a, float b, unsigned& hi, unsigned& lo) {
    __nv_bfloat16 h0, l0, h1, l1;
    bsplit(a, h0, l0); bsplit(b, h1, l1);
    hi = pack_bf2(h0, h1);
    lo = pack_bf2(l0, l1);
}

__device__ __forceinline__ void mma16816(float acc[4],
                                         unsigned a0, unsigned a1, unsigned a2, unsigned a3,
                                         unsigned b0, unsigned b1) {
    asm volatile(
        "mma.sync.aligned.m16n8k16.row.col.f32.bf16.bf16.f32 "
        "{%0,%1,%2,%3}, {%4,%5,%6,%7}, {%8,%9}, {%0,%1,%2,%3};"
        : "+f"(acc[0]), "+f"(acc[1]), "+f"(acc[2]), "+f"(acc[3])
        : "r"(a0), "r"(a1), "r"(a2), "r"(a3), "r"(b0), "r"(b1));
}
__device__ __forceinline__ void ldsm_x4(unsigned& r0, unsigned& r1, unsigned& r2, unsigned& r3,
                                        unsigned addr) {
    asm volatile("ldmatrix.sync.aligned.m8n8.x4.shared.b16 {%0,%1,%2,%3}, [%4];"
                 : "=r"(r0), "=r"(r1), "=r"(r2), "=r"(r3) : "r"(addr));
}

// ---------------- weight pre-split kernel ----------------
__global__ void split_w_kernel(const float* __restrict__ ctr_w, const float* __restrict__ pre_w,
                               const float* __restrict__ suc_w, const float* __restrict__ left_w,
                               const float* __restrict__ right_w, const float* __restrict__ ctr2_w,
                               unsigned* __restrict__ out)
{
    const int m = blockIdx.x;
    const float* W;
    if (m < 6)       W = ctr_w   + (size_t)m        * 16384;
    else if (m < 42) W = pre_w   + (size_t)(m - 6)  * 16384;
    else if (m < 78) W = suc_w   + (size_t)(m - 42) * 16384;
    else if (m < 84) W = left_w  + (size_t)(m - 78) * 16384;
    else if (m < 90) W = right_w + (size_t)(m - 84) * 16384;
    else             W = ctr2_w  + (size_t)(m - 90) * 16384;
    unsigned* hi = out + (size_t)m * 16384;
    unsigned* lo = hi + 8192;
#pragma unroll
    for (int i = 0; i < 32; i++) {
        int p  = threadIdx.x + i * 256;
        int n  = p & 127;
        int kp = p >> 7;
        float w0 = W[(2 * kp) * CC + n];
        float w1 = W[(2 * kp + 1) * CC + n];
        unsigned h, l;
        split2(w0, w1, h, l);
        hi[n * 64 + kp] = h;
        lo[n * 64 + kp] = l;
    }
}

// ---------------- fused gather-MMA-scatter / dense GEMM ----------------
#define WS 68
#define AS 36
#define SW_HI 0
#define SW_LO (128 * WS)
#define SA_HI (2 * 128 * WS)
#define SA_LO (2 * 128 * WS + 128 * AS)
#define SIDX  (2 * 128 * WS + 2 * 128 * AS)
#define SMEM_U32 (SIDX + 256)
#define SMEM_BYTES (SMEM_U32 * 4)

template <bool SCATTER>
__global__ void __launch_bounds__(256, 2)
msg_mma_kernel(const uint4* __restrict__ Ahi,   // [N][16] uint4  (=[N][64] u32)
               const uint4* __restrict__ Alo,
               const unsigned* __restrict__ Wsp, // + blockIdx.y*16384
               const int* __restrict__ u_idx,    // + blockIdx.y*n_rows
               const int* __restrict__ v_idx,
               float* __restrict__ out,
               int n_rows)
{
    extern __shared__ unsigned smem_u[];
    unsigned* sWhi = smem_u + SW_HI;
    unsigned* sWlo = smem_u + SW_LO;
    unsigned* sAhi = smem_u + SA_HI;
    unsigned* sAlo = smem_u + SA_LO;
    int* sU = (int*)(smem_u + SIDX);
    int* sV = sU + 128;

    const int tid  = threadIdx.x;
    const int wid  = tid >> 5;
    const int lane = tid & 31;
    const int tig  = lane & 3;
    const int gid  = lane >> 2;
    const int wr   = wid & 3;
    const int wc   = wid >> 2;

    // ---- stage W (once per CTA): straight uint4 copy into padded layout ----
    {
        const uint4* whi_g = (const uint4*)(Wsp + (size_t)blockIdx.y * 16384);
        const uint4* wlo_g = whi_g + 2048;
#pragma unroll
        for (int j = 0; j < 8; j++) {
            int fi = tid + j * 256;          // 0..2047
            int n  = fi >> 4;
            int q  = fi & 15;
            uint4 v = whi_g[fi];
            *(uint4*)(sWhi + n * WS + q * 4) = v;
            uint4 w = wlo_g[fi];
            *(uint4*)(sWlo + n * WS + q * 4) = w;
        }
    }

    // ldmatrix per-thread base addresses (shared-space bytes)
    unsigned smem_sh = (unsigned)__cvta_generic_to_shared((void*)smem_u);
    const unsigned aA_hi = smem_sh + (SA_HI + (lane & 15) * AS + (lane >> 4) * 4) * 4;
    const unsigned aA_lo = aA_hi + (SA_LO - SA_HI) * 4;
    const unsigned aB_hi = smem_sh + (SW_HI + ((lane & 7) + ((lane & 16) >> 1)) * WS
                                      + ((lane & 8) >> 1)) * 4;
    const unsigned aB_lo = aB_hi + (SW_LO - SW_HI) * 4;

    const int n_tiles = n_rows >> 7;
    const int tpc = n_tiles >> 8;            // gridDim.x == 256
    const int t0 = blockIdx.x * tpc;

#pragma unroll 1
    for (int t = 0; t < tpc; t++) {
        const int tile = t0 + t;
        const int row0 = tile << 7;
        __syncthreads();
        if (SCATTER) {
            if (tid < 128) {
                size_t eb = (size_t)blockIdx.y * n_rows + row0 + tid;
                sU[tid] = u_idx[eb];
                sV[tid] = v_idx[eb];
            }
        }
        __syncthreads();

        float acc[2][8][4];
#pragma unroll
        for (int rt = 0; rt < 2; rt++)
#pragma unroll
            for (int nt = 0; nt < 8; nt++)
#pragma unroll
                for (int q = 0; q < 4; q++) acc[rt][nt][q] = 0.f;

#pragma unroll 1
        for (int kc = 0; kc < 2; kc++) {
            if (kc) __syncthreads();
            // ---- stage A chunk: 128 rows x 32 u32 (hi+lo), pure copies ----
#pragma unroll
            for (int j = 0; j < 4; j++) {
                int fi = tid + j * 256;      // 0..1023
                int r  = fi >> 3;
                int q  = fi & 7;
                int src = SCATTER ? sV[r] : (row0 + r);
                uint4 v = Ahi[(size_t)src * 16 + kc * 8 + q];
                *(uint4*)(sAhi + r * AS + q * 4) = v;
                uint4 w = Alo[(size_t)src * 16 + kc * 8 + q];
                *(uint4*)(sAlo + r * AS + q * 4) = w;
            }
            __syncthreads();

#pragma unroll
            for (int ks = 0; ks < 4; ks++) {
                unsigned ah[2][4], al[2][4];
#pragma unroll
                for (int rt = 0; rt < 2; rt++) {
                    unsigned ofs = ((wr * 32 + rt * 16) * AS + ks * 8) * 4;
                    ldsm_x4(ah[rt][0], ah[rt][1], ah[rt][2], ah[rt][3], aA_hi + ofs);
                    ldsm_x4(al[rt][0], al[rt][1], al[rt][2], al[rt][3], aA_lo + ofs);
                }
#pragma unroll
                for (int nt2 = 0; nt2 < 4; nt2++) {
                    unsigned bh[4], bl[4];
                    unsigned bofs = ((wc * 64 + nt2 * 16) * WS + kc * 32 + ks * 8) * 4;
                    ldsm_x4(bh[0], bh[1], bh[2], bh[3], aB_hi + bofs);
                    ldsm_x4(bl[0], bl[1], bl[2], bl[3], aB_lo + bofs);
#pragma unroll
                    for (int half = 0; half < 2; half++) {
                        const int nt = nt2 * 2 + half;
                        unsigned b0h = bh[2 * half], b1h = bh[2 * half + 1];
                        unsigned b0l = bl[2 * half], b1l = bl[2 * half + 1];
#pragma unroll
                        for (int rt = 0; rt < 2; rt++) {
                            mma16816(acc[rt][nt], ah[rt][0], ah[rt][1], ah[rt][2], ah[rt][3], b0h, b1h);
                            mma16816(acc[rt][nt], ah[rt][0], ah[rt][1], ah[rt][2], ah[rt][3], b0l, b1l);
                            mma16816(acc[rt][nt], al[rt][0], al[rt][1], al[rt][2], al[rt][3], b0h, b1h);
                        }
                    }
                }
            }
        }

        // ---- epilogue: shfl-assemble float4 runs; red.v4 scatter or STG.128 ----
        const bool even = (tig & 1) == 0;
        const int colofs = (tig & 2) ? 4 : 0;
#pragma unroll
        for (int rt = 0; rt < 2; rt++) {
            const int arow = wr * 32 + rt * 16 + gid + (even ? 0 : 8);
            float* base;
            if (SCATTER) base = out + (size_t)sU[arow] * CC;
            else         base = out + (size_t)(row0 + arow) * CC;
#pragma unroll
            for (int nt = 0; nt < 8; nt++) {
                float c0 = acc[rt][nt][0], c1 = acc[rt][nt][1];
                float c2 = acc[rt][nt][2], c3 = acc[rt][nt][3];
                float e0 = __shfl_xor_sync(0xffffffffu, c0, 1);
                float e1 = __shfl_xor_sync(0xffffffffu, c1, 1);
                float e2 = __shfl_xor_sync(0xffffffffu, c2, 1);
                float e3 = __shfl_xor_sync(0xffffffffu, c3, 1);
                float x0, x1, x2, x3;
                if (even) { x0 = c0; x1 = c1; x2 = e0; x3 = e1; }
                else      { x0 = e2; x1 = e3; x2 = c2; x3 = c3; }
                float* p = base + wc * 64 + nt * 8 + colofs;
                if (SCATTER) {
                    asm volatile("red.global.add.v4.f32 [%0], {%1,%2,%3,%4};"
                                 :: "l"(p), "f"(x0), "f"(x1), "f"(x2), "f"(x3) : "memory");
                } else {
                    float4 v; v.x = x0; v.y = x1; v.z = x2; v.w = x3;
                    *(float4*)p = v;
                }
            }
        }
    }
}

// ---------------- input encoder (+ split write) ----------------
__global__ void encoder_kernel(const float* __restrict__ ctrs, const float* __restrict__ feats,
                               const float* __restrict__ icw0, const float* __restrict__ icb0,
                               const float* __restrict__ icw1, const float* __restrict__ icg,
                               const float* __restrict__ icbt,
                               const float* __restrict__ ifw0, const float* __restrict__ ifb0,
                               const float* __restrict__ ifw1, const float* __restrict__ ifg,
                               const float* __restrict__ ifbt,
                               float* __restrict__ out,
                               unsigned* __restrict__ ohi, unsigned* __restrict__ olo)
{
    const int tid = threadIdx.x;
    const int r = tid >> 7;
    const int c = tid & 127;
    const int row = (blockIdx.x << 1) + r;
    const int warp = (tid >> 5) & 3;
    const int lane = tid & 31;
    __shared__ float sh[2][CC];
    __shared__ float sred[2][2][4];

    float ysum = 0.f;
#pragma unroll
    for (int br = 0; br < 2; br++) {
        const float* x  = br ? feats : ctrs;
        const float* w0 = br ? ifw0 : icw0;
        const float* b0 = br ? ifb0 : icb0;
        const float* w1 = br ? ifw1 : icw1;
        const float* g  = br ? ifg  : icg;
        const float* bt = br ? ifbt : icbt;
        const float x0 = x[row * 2 + 0];
        const float x1 = x[row * 2 + 1];
        float h = fmaxf(fmaf(x1, w0[CC + c], fmaf(x0, w0[c], b0[c])), 0.f);
        __syncthreads();
        sh[r][c] = h;
        __syncthreads();
        float z = 0.f;
#pragma unroll 8
        for (int k = 0; k < CC; k++) z = fmaf(sh[r][k], w1[k * CC + c], z);
        float s = z, sq = z * z;
#pragma unroll
        for (int o = 16; o > 0; o >>= 1) {
            s  += __shfl_xor_sync(0xffffffffu, s, o);
            sq += __shfl_xor_sync(0xffffffffu, sq, o);
        }
        if (lane == 0) { sred[r][0][warp] = s; sred[r][1][warp] = sq; }
        __syncthreads();
        float mu  = (sred[r][0][0] + sred[r][0][1] + sred[r][0][2] + sred[r][0][3]) * (1.f / CC);
        float ms  = (sred[r][1][0] + sred[r][1][1] + sred[r][1][2] + sred[r][1][3]) * (1.f / CC);
        float var = ms - mu * mu;
        ysum += (z - mu) * rsqrtf(var + GN_EPS) * g[c] + bt[c];
    }
    float y = fmaxf(ysum, 0.f);
    out[(size_t)row * CC + c] = y;
    float yn = __shfl_down_sync(0xffffffffu, y, 1);
    if ((c & 1) == 0) {
        unsigned h, l; split2(y, yn, h, l);
        ohi[(size_t)row * 64 + (c >> 1)] = h;
        olo[(size_t)row * 64 + (c >> 1)] = l;
    }
}

// ---------------- GN + relu -> split planes only ----------------
__global__ void norm_relu_kernel(const float* __restrict__ in,
                                 const float* __restrict__ g, const float* __restrict__ b,
                                 unsigned* __restrict__ ohi, unsigned* __restrict__ olo)
{
    const int tid = threadIdx.x;
    const int r = tid >> 7, c = tid & 127;
    const size_t row = (size_t)(blockIdx.x << 1) + r;
    const int warp = (tid >> 5) & 3, lane = tid & 31;
    __shared__ float sred[2][2][4];
    float z = in[row * CC + c];
    float s = z, sq = z * z;
#pragma unroll
    for (int o = 16; o > 0; o >>= 1) {
        s  += __shfl_xor_sync(0xffffffffu, s, o);
        sq += __shfl_xor_sync(0xffffffffu, sq, o);
    }
    if (lane == 0) { sred[r][0][warp] = s; sred[r][1][warp] = sq; }
    __syncthreads();
    float mu  = (sred[r][0][0] + sred[r][0][1] + sred[r][0][2] + sred[r][0][3]) * (1.f / CC);
    float ms  = (sred[r][1][0] + sred[r][1][1] + sred[r][1][2] + sred[r][1][3]) * (1.f / CC);
    float var = ms - mu * mu;
    float y = fmaxf((z - mu) * rsqrtf(var + GN_EPS) * g[c] + b[c], 0.f);
    float yn = __shfl_down_sync(0xffffffffu, y, 1);
    if ((c & 1) == 0) {
        unsigned h, l; split2(y, yn, h, l);
        ohi[row * 64 + (c >> 1)] = h;
        olo[row * 64 + (c >> 1)] = l;
    }
}

// ---------------- GN + residual + relu -> f32 + split planes ----------------
__global__ void norm_res_kernel(const float* __restrict__ in,
                                const float* __restrict__ g, const float* __restrict__ b,
                                const float* __restrict__ iden, float* __restrict__ out,
                                unsigned* __restrict__ ohi, unsigned* __restrict__ olo)
{
    const int tid = threadIdx.x;
    const int r = tid >> 7, c = tid & 127;
    const size_t row = (size_t)(blockIdx.x << 1) + r;
    const int warp = (tid >> 5) & 3, lane = tid & 31;
    __shared__ float sred[2][2][4];
    float z = in[row * CC + c];
    float s = z, sq = z * z;
#pragma unroll
    for (int o = 16; o > 0; o >>= 1) {
        s  += __shfl_xor_sync(0xffffffffu, s, o);
        sq += __shfl_xor_sync(0xffffffffu, sq, o);
    }
    if (lane == 0) { sred[r][0][warp] = s; sred[r][1][warp] = sq; }
    __syncthreads();
    float mu  = (sred[r][0][0] + sred[r][0][1] + sred[r][0][2] + sred[r][0][3]) * (1.f / CC);
    float ms  = (sred[r][1][0] + sred[r][1][1] + sred[r][1][2] + sred[r][1][3]) * (1.f / CC);
    float var = ms - mu * mu;
    float y = (z - mu) * rsqrtf(var + GN_EPS) * g[c] + b[c];
    y = fmaxf(y + iden[row * CC + c], 0.f);
    out[row * CC + c] = y;
    float yn = __shfl_down_sync(0xffffffffu, y, 1);
    if ((c & 1) == 0) {
        unsigned h, l; split2(y, yn, h, l);
        ohi[row * 64 + (c >> 1)] = h;
        olo[row * 64 + (c >> 1)] = l;
    }
}

extern "C" void kernel_launch(void* const* d_in, const int* in_sizes, int n_in,
                              void* d_out, int out_size)
{
    const float* ctrs    = (const float*)d_in[0];
    const float* feats   = (const float*)d_in[1];
    const int*   pre_u   = (const int*)d_in[2];
    const int*   pre_v   = (const int*)d_in[3];
    const int*   suc_u   = (const int*)d_in[4];
    const int*   suc_v   = (const int*)d_in[5];
    const int*   left_u  = (const int*)d_in[6];
    const int*   left_v  = (const int*)d_in[7];
    const int*   right_u = (const int*)d_in[8];
    const int*   right_v = (const int*)d_in[9];
    const float* ic_w0   = (const float*)d_in[10];
    const float* ic_b0   = (const float*)d_in[11];
    const float* ic_w1   = (const float*)d_in[12];
    const float* ic_g    = (const float*)d_in[13];
    const float* ic_bt   = (const float*)d_in[14];
    const float* if_w0   = (const float*)d_in[15];
    const float* if_b0   = (const float*)d_in[16];
    const float* if_w1   = (const float*)d_in[17];
    const float* if_g    = (const float*)d_in[18];
    const float* if_bt   = (const float*)d_in[19];
    const float* ctr_w   = (const float*)d_in[20];
    const float* pre_w   = (const float*)d_in[21];
    const float* suc_w   = (const float*)d_in[22];
    const float* left_w  = (const float*)d_in[23];
    const float* right_w = (const float*)d_in[24];
    const float* norm_g  = (const float*)d_in[25];
    const float* norm_b  = (const float*)d_in[26];
    const float* ctr2_w  = (const float*)d_in[27];
    const float* ctr2_g  = (const float*)d_in[28];
    const float* ctr2_b  = (const float*)d_in[29];

    float *bufA, *bufB, *temp;
    unsigned *fhi, *flo, *hhi, *hlo, *wsp;
    cudaGetSymbolAddress((void**)&bufA, g_bufA);
    cudaGetSymbolAddress((void**)&bufB, g_bufB);
    cudaGetSymbolAddress((void**)&temp, g_temp);
    cudaGetSymbolAddress((void**)&fhi, g_fhi);
    cudaGetSymbolAddress((void**)&flo, g_flo);
    cudaGetSymbolAddress((void**)&hhi, g_hhi);
    cudaGetSymbolAddress((void**)&hlo, g_hlo);
    cudaGetSymbolAddress((void**)&wsp, g_wsp);

    cudaFuncSetAttribute(msg_mma_kernel<false>, cudaFuncAttributeMaxDynamicSharedMemorySize, SMEM_BYTES);
    cudaFuncSetAttribute(msg_mma_kernel<true>,  cudaFuncAttributeMaxDynamicSharedMemorySize, SMEM_BYTES);

    // one-time weight split (96 matrices)
    split_w_kernel<<<96, 256>>>(ctr_w, pre_w, suc_w, left_w, right_w, ctr2_w, wsp);

    // initial feat -> bufA (f32) + split planes
    encoder_kernel<<<NN / 2, 256>>>(ctrs, feats,
                                    ic_w0, ic_b0, ic_w1, ic_g, ic_bt,
                                    if_w0, if_b0, if_w1, if_g, if_bt,
                                    bufA, fhi, flo);

    const uint4* fhi4 = (const uint4*)fhi;
    const uint4* flo4 = (const uint4*)flo;
    const uint4* hhi4 = (const uint4*)hhi;
    const uint4* hlo4 = (const uint4*)hlo;

    float* fin = bufA;
    for (int i = 0; i < BB; i++) {
        // temp = feat @ ctr_w[i]  (slot i)
        msg_mma_kernel<false><<<dim3(256, 1), 256, SMEM_BYTES>>>(
            fhi4, flo4, wsp + (size_t)i * 16384, nullptr, nullptr, temp, NN);
        // pre (slots 6 + i*6 ..), suc (42 + i*6 ..)
        msg_mma_kernel<true><<<dim3(256, SS), 256, SMEM_BYTES>>>(
            fhi4, flo4, wsp + (size_t)(6 + i * 6) * 16384, pre_u, pre_v, temp, EE);
        msg_mma_kernel<true><<<dim3(256, SS), 256, SMEM_BYTES>>>(
            fhi4, flo4, wsp + (size_t)(42 + i * 6) * 16384, suc_u, suc_v, temp, EE);
        // left (78+i), right (84+i)
        msg_mma_kernel<true><<<dim3(256, 1), 256, SMEM_BYTES>>>(
            fhi4, flo4, wsp + (size_t)(78 + i) * 16384, left_u, left_v, temp, ELE);
        msg_mma_kernel<true><<<dim3(256, 1), 256, SMEM_BYTES>>>(
            fhi4, flo4, wsp + (size_t)(84 + i) * 16384, right_u, right_v, temp, ELE);
        // h = relu(GN(temp)) -> split planes only
        norm_relu_kernel<<<NN / 2, 256>>>(temp, norm_g + i * CC, norm_b + i * CC, hhi, hlo);
        // temp = h @ ctr2_w[i]  (slot 90+i)
        msg_mma_kernel<false><<<dim3(256, 1), 256, SMEM_BYTES>>>(
            hhi4, hlo4, wsp + (size_t)(90 + i) * 16384, nullptr, nullptr, temp, NN);
        // feat = relu(GN(temp) + identity) -> f32 + split planes
        float* dst = (i == BB - 1) ? (float*)d_out : ((fin == bufA) ? bufB : bufA);
        norm_res_kernel<<<NN / 2, 256>>>(temp, ctr2_g + i * CC, ctr2_b + i * CC, fin, dst, fhi, flo);
        fin = dst;
    }
}

// round 4
// speedup vs baseline: 2.3302x; 1.2553x over previous
#include <cuda_runtime.h>
#include <cuda_bf16.h>

#define NN  131072
#define CC  128
#define SS  6
#define BB  6
#define EE  131072
#define ELE 32768
#define GN_EPS 1e-5f

// ---------------- device scratch ----------------
static __device__ float g_bufA[(size_t)NN * CC];
static __device__ float g_bufB[(size_t)NN * CC];
static __device__ float g_temp[(size_t)NN * CC];
// split planes: [N][64] u32 (bf16x2 pairs), hi then lo
static __device__ unsigned g_fhi[(size_t)NN * 64];
static __device__ unsigned g_flo[(size_t)NN * 64];
static __device__ unsigned g_hhi[(size_t)NN * 64];
static __device__ unsigned g_hlo[(size_t)NN * 64];
// split weights: [96][hi 8192 | lo 8192] u32, layout [n=128][kp=64]
static __device__ unsigned g_wsp[(size_t)96 * 16384];

// ---------------- bf16 split helpers ----------------
__device__ __forceinline__ unsigned pack_bf2(__nv_bfloat16 lo16, __nv_bfloat16 hi16) {
    __nv_bfloat162 t(lo16, hi16);
    return *reinterpret_cast<unsigned*>(&t);
}
__device__ __forceinline__ void bsplit(float x, __nv_bfloat16& h, __nv_bfloat16& l) {
    h = __float2bfloat16(x);
    l = __float2bfloat16(x - __bfloat162float(h));
}
__device__ __forceinline__ void split2(float a, float b, unsigned& hi, unsigned& lo) {
    __nv_bfloat16 h0, l0, h1, l1;
    bsplit(a, h0, l0); bsplit(b, h1, l1);
    hi = pack_bf2(h0, h1);
    lo = pack_bf2(l0, l1);
}

__device__ __forceinline__ void mma16816(float acc[4],
                                         unsigned a0, unsigned a1, unsigned a2, unsigned a3,
                                         unsigned b0, unsigned b1) {
    asm volatile(
        "mma.sync.aligned.m16n8k16.row.col.f32.bf16.bf16.f32 "
        "{%0,%1,%2,%3}, {%4,%5,%6,%7}, {%8,%9}, {%0,%1,%2,%3};"
        : "+f"(acc[0]), "+f"(acc[1]), "+f"(acc[2]), "+f"(acc[3])
        : "r"(a0), "r"(a1), "r"(a2), "r"(a3), "r"(b0), "r"(b1));
}
__device__ __forceinline__ void ldsm_x4(unsigned& r0, unsigned& r1, unsigned& r2, unsigned& r3,
                                        unsigned addr) {
    asm volatile("ldmatrix.sync.aligned.m8n8.x4.shared.b16 {%0,%1,%2,%3}, [%4];"
                 : "=r"(r0), "=r"(r1), "=r"(r2), "=r"(r3) : "r"(addr));
}
__device__ __forceinline__ void cp16(unsigned dst_sh, const void* src) {
    asm volatile("cp.async.cg.shared.global [%0], [%1], 16;" :: "r"(dst_sh), "l"(src));
}

// ---------------- weight pre-split kernel ----------------
__global__ void split_w_kernel(const float* __restrict__ ctr_w, const float* __restrict__ pre_w,
                               const float* __restrict__ suc_w, const float* __restrict__ left_w,
                               const float* __restrict__ right_w, const float* __restrict__ ctr2_w,
                               unsigned* __restrict__ out)
{
    const int m = blockIdx.x;
    const float* W;
    if (m < 6)       W = ctr_w   + (size_t)m        * 16384;
    else if (m < 42) W = pre_w   + (size_t)(m - 6)  * 16384;
    else if (m < 78) W = suc_w   + (size_t)(m - 42) * 16384;
    else if (m < 84) W = left_w  + (size_t)(m - 78) * 16384;
    else if (m < 90) W = right_w + (size_t)(m - 84) * 16384;
    else             W = ctr2_w  + (size_t)(m - 90) * 16384;
    unsigned* hi = out + (size_t)m * 16384;
    unsigned* lo = hi + 8192;
#pragma unroll
    for (int i = 0; i < 32; i++) {
        int p  = threadIdx.x + i * 256;
        int n  = p & 127;
        int kp = p >> 7;
        float w0 = W[(2 * kp) * CC + n];
        float w1 = W[(2 * kp + 1) * CC + n];
        unsigned h, l;
        split2(w0, w1, h, l);
        hi[n * 64 + kp] = h;
        lo[n * 64 + kp] = l;
    }
}

// ---------------- pipelined gather-MMA-scatter / dense GEMM ----------------
// smem (u32 units):
//   sW   [0,      16384): plane*8192 + n*64 + swz-chunks     (swz: c^=(n&7))
//   sA   [16384,  49152): slot*16384 + plane*8192 + r*64 + swz-chunks
//   sIdx [49152,  49664): slot*256 + {u:0-127, v:128-255}
#define SMEM_U32 49664
#define SMEM_BYTES (SMEM_U32 * 4)

template <bool SCATTER>
__device__ __forceinline__ void stage_A(unsigned shb, int slot,
                                        const uint4* __restrict__ Ahi,
                                        const uint4* __restrict__ Alo,
                                        const int* sV, int row0, int tid)
{
    const unsigned dstbase = shb + ((16384u + (unsigned)slot * 16384u) << 2);
#pragma unroll
    for (int j = 0; j < 8; j++) {
        int fi = tid + j * 512;          // 0..4095 uint4 chunks
        int plane = fi >> 11;
        int p = fi & 2047;
        int r = p >> 4;
        int c = p & 15;
        int src_row = SCATTER ? sV[r] : (row0 + r);
        const uint4* src = (plane ? Alo : Ahi) + (size_t)src_row * 16 + c;
        unsigned dst = dstbase + ((unsigned)(plane * 8192 + r * 64 + ((c ^ (r & 7)) << 2)) << 2);
        cp16(dst, src);
    }
}

template <bool SCATTER>
__global__ void __launch_bounds__(512, 1)
msg_mma_kernel(const uint4* __restrict__ Ahi,    // [N][16] uint4
               const uint4* __restrict__ Alo,
               const unsigned* __restrict__ Wsp,  // + blockIdx.y*16384
               const int* __restrict__ u_idx,     // + blockIdx.y*n_rows
               const int* __restrict__ v_idx,
               float* __restrict__ out,
               int n_rows)
{
    extern __shared__ unsigned smem_u[];
    int* sIdx = (int*)(smem_u + 49152);

    const int tid  = threadIdx.x;
    const int lane = tid & 31;
    const int wid  = tid >> 5;
    const int wr   = wid & 3;        // 32-row group
    const int wc   = wid >> 2;       // 32-col group
    const int tig  = lane & 3;
    const int gid  = lane >> 2;

    const int n_tiles = n_rows >> 7;
    int tile = blockIdx.x;
    if (tile >= n_tiles) return;

    const unsigned shb = (unsigned)__cvta_generic_to_shared((void*)smem_u);

    // ---- stage W (once, swizzled) ----
    {
        const uint4* wg = (const uint4*)(Wsp + (size_t)blockIdx.y * 16384);
#pragma unroll
        for (int j = 0; j < 8; j++) {
            int fi = tid + j * 512;      // 0..4095
            int plane = fi >> 11;
            int p = fi & 2047;
            int n = p >> 4;
            int c = p & 15;
            uint4 v = wg[fi];
            *(uint4*)(smem_u + plane * 8192 + n * 64 + ((c ^ (n & 7)) << 2)) = v;
        }
    }

    // ---- prologue: idx for first tile + stage slot 0 ----
    if (SCATTER && tid < 256) {
        const int* src = (tid < 128) ? u_idx : v_idx;
        sIdx[tid] = src[(size_t)blockIdx.y * n_rows + (tile << 7) + (tid & 127)];
    }
    __syncthreads();
    stage_A<SCATTER>(shb, 0, Ahi, Alo, sIdx + 128, tile << 7, tid);
    asm volatile("cp.async.commit_group;" ::: "memory");

    // ---- per-thread fragment address bases ----
    const int hi4A = lane >> 4;
    const int hi4B = (lane & 8) >> 3;
    unsigned baseA[2][2], baseB[2][2];
    int swzA[2], swzB[2];
#pragma unroll
    for (int rt = 0; rt < 2; rt++) {
        int rr = wr * 32 + rt * 16 + (lane & 15);
        swzA[rt] = rr & 7;
#pragma unroll
        for (int pl = 0; pl < 2; pl++)
            baseA[rt][pl] = shb + ((unsigned)(16384 + pl * 8192 + rr * 64) << 2);
    }
#pragma unroll
    for (int nt2 = 0; nt2 < 2; nt2++) {
        int nn = wc * 32 + nt2 * 16 + (lane & 7) + ((lane & 16) >> 1);
        swzB[nt2] = nn & 7;
#pragma unroll
        for (int pl = 0; pl < 2; pl++)
            baseB[nt2][pl] = shb + ((unsigned)(pl * 8192 + nn * 64) << 2);
    }

    int slot = 0;
#pragma unroll 1
    while (true) {
        const int row0 = tile << 7;
        const int next = tile + gridDim.x;
        const bool has_next = (next < n_tiles);

        int nreg = 0;
        if (SCATTER && has_next && tid < 256) {
            const int* src = (tid < 128) ? u_idx : v_idx;
            nreg = src[(size_t)blockIdx.y * n_rows + (next << 7) + (tid & 127)];
        }
        asm volatile("cp.async.wait_group 0;" ::: "memory");
        if (SCATTER && has_next && tid < 256)
            sIdx[(slot ^ 1) * 256 + tid] = nreg;
        __syncthreads();
        if (has_next) {
            stage_A<SCATTER>(shb, slot ^ 1, Ahi, Alo, sIdx + (slot ^ 1) * 256 + 128,
                             next << 7, tid);
            asm volatile("cp.async.commit_group;" ::: "memory");
        }

        // ---- compute tile from current slot ----
        const unsigned slotb = (unsigned)slot << 16;   // slot*16384 u32 *4 bytes
        float acc[2][4][4];
#pragma unroll
        for (int rt = 0; rt < 2; rt++)
#pragma unroll
            for (int nt = 0; nt < 4; nt++)
#pragma unroll
                for (int q = 0; q < 4; q++) acc[rt][nt][q] = 0.f;

#pragma unroll
        for (int ks = 0; ks < 8; ks++) {
            unsigned ah[2][4], al[2][4];
#pragma unroll
            for (int rt = 0; rt < 2; rt++) {
                unsigned ch = (unsigned)(((2 * ks + hi4A) ^ swzA[rt]) << 4);
                ldsm_x4(ah[rt][0], ah[rt][1], ah[rt][2], ah[rt][3], baseA[rt][0] + slotb + ch);
                ldsm_x4(al[rt][0], al[rt][1], al[rt][2], al[rt][3], baseA[rt][1] + slotb + ch);
            }
#pragma unroll
            for (int nt2 = 0; nt2 < 2; nt2++) {
                unsigned bh[4], bl[4];
                unsigned ch = (unsigned)(((2 * ks + hi4B) ^ swzB[nt2]) << 4);
                ldsm_x4(bh[0], bh[1], bh[2], bh[3], baseB[nt2][0] + ch);
                ldsm_x4(bl[0], bl[1], bl[2], bl[3], baseB[nt2][1] + ch);
#pragma unroll
                for (int half = 0; half < 2; half++) {
                    const int nt = nt2 * 2 + half;
                    unsigned b0h = bh[2 * half], b1h = bh[2 * half + 1];
                    unsigned b0l = bl[2 * half], b1l = bl[2 * half + 1];
#pragma unroll
                    for (int rt = 0; rt < 2; rt++) {
                        mma16816(acc[rt][nt], ah[rt][0], ah[rt][1], ah[rt][2], ah[rt][3], b0h, b1h);
                        mma16816(acc[rt][nt], ah[rt][0], ah[rt][1], ah[rt][2], ah[rt][3], b0l, b1l);
                        mma16816(acc[rt][nt], al[rt][0], al[rt][1], al[rt][2], al[rt][3], b0h, b1h);
                    }
                }
            }
        }

        // ---- epilogue ----
        const bool even = (tig & 1) == 0;
        const int colofs = (tig & 2) ? 4 : 0;
#pragma unroll
        for (int rt = 0; rt < 2; rt++) {
            const int arow = wr * 32 + rt * 16 + gid + (even ? 0 : 8);
            float* base;
            if (SCATTER) base = out + (size_t)sIdx[slot * 256 + arow] * CC;
            else         base = out + (size_t)(row0 + arow) * CC;
#pragma unroll
            for (int nt = 0; nt < 4; nt++) {
                float c0 = acc[rt][nt][0], c1 = acc[rt][nt][1];
                float c2 = acc[rt][nt][2], c3 = acc[rt][nt][3];
                float e0 = __shfl_xor_sync(0xffffffffu, c0, 1);
                float e1 = __shfl_xor_sync(0xffffffffu, c1, 1);
                float e2 = __shfl_xor_sync(0xffffffffu, c2, 1);
                float e3 = __shfl_xor_sync(0xffffffffu, c3, 1);
                float x0, x1, x2, x3;
                if (even) { x0 = c0; x1 = c1; x2 = e0; x3 = e1; }
                else      { x0 = e2; x1 = e3; x2 = c2; x3 = c3; }
                float* p = base + wc * 32 + nt * 8 + colofs;
                if (SCATTER) {
                    asm volatile("red.global.add.v4.f32 [%0], {%1,%2,%3,%4};"
                                 :: "l"(p), "f"(x0), "f"(x1), "f"(x2), "f"(x3) : "memory");
                } else {
                    float4 v; v.x = x0; v.y = x1; v.z = x2; v.w = x3;
                    *(float4*)p = v;
                }
            }
        }

        if (!has_next) break;
        if (SCATTER) __syncthreads();   // protect sIdx[slot] (read above) from next iter's write
        tile = next;
        slot ^= 1;
    }
}

// ---------------- input encoder (+ split write) ----------------
__global__ void encoder_kernel(const float* __restrict__ ctrs, const float* __restrict__ feats,
                               const float* __restrict__ icw0, const float* __restrict__ icb0,
                               const float* __restrict__ icw1, const float* __restrict__ icg,
                               const float* __restrict__ icbt,
                               const float* __restrict__ ifw0, const float* __restrict__ ifb0,
                               const float* __restrict__ ifw1, const float* __restrict__ ifg,
                               const float* __restrict__ ifbt,
                               float* __restrict__ out,
                               unsigned* __restrict__ ohi, unsigned* __restrict__ olo)
{
    const int tid = threadIdx.x;
    const int r = tid >> 7;
    const int c = tid & 127;
    const int row = (blockIdx.x << 1) + r;
    const int warp = (tid >> 5) & 3;
    const int lane = tid & 31;
    __shared__ float sh[2][CC];
    __shared__ float sred[2][2][4];

    float ysum = 0.f;
#pragma unroll
    for (int br = 0; br < 2; br++) {
        const float* x  = br ? feats : ctrs;
        const float* w0 = br ? ifw0 : icw0;
        const float* b0 = br ? ifb0 : icb0;
        const float* w1 = br ? ifw1 : icw1;
        const float* g  = br ? ifg  : icg;
        const float* bt = br ? ifbt : icbt;
        const float x0 = x[row * 2 + 0];
        const float x1 = x[row * 2 + 1];
        float h = fmaxf(fmaf(x1, w0[CC + c], fmaf(x0, w0[c], b0[c])), 0.f);
        __syncthreads();
        sh[r][c] = h;
        __syncthreads();
        float z = 0.f;
#pragma unroll 8
        for (int k = 0; k < CC; k++) z = fmaf(sh[r][k], w1[k * CC + c], z);
        float s = z, sq = z * z;
#pragma unroll
        for (int o = 16; o > 0; o >>= 1) {
            s  += __shfl_xor_sync(0xffffffffu, s, o);
            sq += __shfl_xor_sync(0xffffffffu, sq, o);
        }
        if (lane == 0) { sred[r][0][warp] = s; sred[r][1][warp] = sq; }
        __syncthreads();
        float mu  = (sred[r][0][0] + sred[r][0][1] + sred[r][0][2] + sred[r][0][3]) * (1.f / CC);
        float ms  = (sred[r][1][0] + sred[r][1][1] + sred[r][1][2] + sred[r][1][3]) * (1.f / CC);
        float var = ms - mu * mu;
        ysum += (z - mu) * rsqrtf(var + GN_EPS) * g[c] + bt[c];
    }
    float y = fmaxf(ysum, 0.f);
    out[(size_t)row * CC + c] = y;
    float yn = __shfl_down_sync(0xffffffffu, y, 1);
    if ((c & 1) == 0) {
        unsigned h, l; split2(y, yn, h, l);
        ohi[(size_t)row * 64 + (c >> 1)] = h;
        olo[(size_t)row * 64 + (c >> 1)] = l;
    }
}

// ---------------- GN + relu -> split planes only ----------------
__global__ void norm_relu_kernel(const float* __restrict__ in,
                                 const float* __restrict__ g, const float* __restrict__ b,
                                 unsigned* __restrict__ ohi, unsigned* __restrict__ olo)
{
    const int tid = threadIdx.x;
    const int r = tid >> 7, c = tid & 127;
    const size_t row = (size_t)(blockIdx.x << 1) + r;
    const int warp = (tid >> 5) & 3, lane = tid & 31;
    __shared__ float sred[2][2][4];
    float z = in[row * CC + c];
    float s = z, sq = z * z;
#pragma unroll
    for (int o = 16; o > 0; o >>= 1) {
        s  += __shfl_xor_sync(0xffffffffu, s, o);
        sq += __shfl_xor_sync(0xffffffffu, sq, o);
    }
    if (lane == 0) { sred[r][0][warp] = s; sred[r][1][warp] = sq; }
    __syncthreads();
    float mu  = (sred[r][0][0] + sred[r][0][1] + sred[r][0][2] + sred[r][0][3]) * (1.f / CC);
    float ms  = (sred[r][1][0] + sred[r][1][1] + sred[r][1][2] + sred[r][1][3]) * (1.f / CC);
    float var = ms - mu * mu;
    float y = fmaxf((z - mu) * rsqrtf(var + GN_EPS) * g[c] + b[c], 0.f);
    float yn = __shfl_down_sync(0xffffffffu, y, 1);
    if ((c & 1) == 0) {
        unsigned h, l; split2(y, yn, h, l);
        ohi[row * 64 + (c >> 1)] = h;
        olo[row * 64 + (c >> 1)] = l;
    }
}

// ---------------- GN + residual + relu -> f32 + split planes ----------------
__global__ void norm_res_kernel(const float* __restrict__ in,
                                const float* __restrict__ g, const float* __restrict__ b,
                                const float* __restrict__ iden, float* __restrict__ out,
                                unsigned* __restrict__ ohi, unsigned* __restrict__ olo)
{
    const int tid = threadIdx.x;
    const int r = tid >> 7, c = tid & 127;
    const size_t row = (size_t)(blockIdx.x << 1) + r;
    const int warp = (tid >> 5) & 3, lane = tid & 31;
    __shared__ float sred[2][2][4];
    float z = in[row * CC + c];
    float s = z, sq = z * z;
#pragma unroll
    for (int o = 16; o > 0; o >>= 1) {
        s  += __shfl_xor_sync(0xffffffffu, s, o);
        sq += __shfl_xor_sync(0xffffffffu, sq, o);
    }
    if (lane == 0) { sred[r][0][warp] = s; sred[r][1][warp] = sq; }
    __syncthreads();
    float mu  = (sred[r][0][0] + sred[r][0][1] + sred[r][0][2] + sred[r][0][3]) * (1.f / CC);
    float ms  = (sred[r][1][0] + sred[r][1][1] + sred[r][1][2] + sred[r][1][3]) * (1.f / CC);
    float var = ms - mu * mu;
    float y = (z - mu) * rsqrtf(var + GN_EPS) * g[c] + b[c];
    y = fmaxf(y + iden[row * CC + c], 0.f);
    out[row * CC + c] = y;
    float yn = __shfl_down_sync(0xffffffffu, y, 1);
    if ((c & 1) == 0) {
        unsigned h, l; split2(y, yn, h, l);
        ohi[row * 64 + (c >> 1)] = h;
        olo[row * 64 + (c >> 1)] = l;
    }
}

extern "C" void kernel_launch(void* const* d_in, const int* in_sizes, int n_in,
                              void* d_out, int out_size)
{
    const float* ctrs    = (const float*)d_in[0];
    const float* feats   = (const float*)d_in[1];
    const int*   pre_u   = (const int*)d_in[2];
    const int*   pre_v   = (const int*)d_in[3];
    const int*   suc_u   = (const int*)d_in[4];
    const int*   suc_v   = (const int*)d_in[5];
    const int*   left_u  = (const int*)d_in[6];
    const int*   left_v  = (const int*)d_in[7];
    const int*   right_u = (const int*)d_in[8];
    const int*   right_v = (const int*)d_in[9];
    const float* ic_w0   = (const float*)d_in[10];
    const float* ic_b0   = (const float*)d_in[11];
    const float* ic_w1   = (const float*)d_in[12];
    const float* ic_g    = (const float*)d_in[13];
    const float* ic_bt   = (const float*)d_in[14];
    const float* if_w0   = (const float*)d_in[15];
    const float* if_b0   = (const float*)d_in[16];
    const float* if_w1   = (const float*)d_in[17];
    const float* if_g    = (const float*)d_in[18];
    const float* if_bt   = (const float*)d_in[19];
    const float* ctr_w   = (const float*)d_in[20];
    const float* pre_w   = (const float*)d_in[21];
    const float* suc_w   = (const float*)d_in[22];
    const float* left_w  = (const float*)d_in[23];
    const float* right_w = (const float*)d_in[24];
    const float* norm_g  = (const float*)d_in[25];
    const float* norm_b  = (const float*)d_in[26];
    const float* ctr2_w  = (const float*)d_in[27];
    const float* ctr2_g  = (const float*)d_in[28];
    const float* ctr2_b  = (const float*)d_in[29];

    float *bufA, *bufB, *temp;
    unsigned *fhi, *flo, *hhi, *hlo, *wsp;
    cudaGetSymbolAddress((void**)&bufA, g_bufA);
    cudaGetSymbolAddress((void**)&bufB, g_bufB);
    cudaGetSymbolAddress((void**)&temp, g_temp);
    cudaGetSymbolAddress((void**)&fhi, g_fhi);
    cudaGetSymbolAddress((void**)&flo, g_flo);
    cudaGetSymbolAddress((void**)&hhi, g_hhi);
    cudaGetSymbolAddress((void**)&hlo, g_hlo);
    cudaGetSymbolAddress((void**)&wsp, g_wsp);

    cudaFuncSetAttribute(msg_mma_kernel<false>, cudaFuncAttributeMaxDynamicSharedMemorySize, SMEM_BYTES);
    cudaFuncSetAttribute(msg_mma_kernel<true>,  cudaFuncAttributeMaxDynamicSharedMemorySize, SMEM_BYTES);

    // one-time weight split (96 matrices)
    split_w_kernel<<<96, 256>>>(ctr_w, pre_w, suc_w, left_w, right_w, ctr2_w, wsp);

    // initial feat -> bufA (f32) + split planes
    encoder_kernel<<<NN / 2, 256>>>(ctrs, feats,
                                    ic_w0, ic_b0, ic_w1, ic_g, ic_bt,
                                    if_w0, if_b0, if_w1, if_g, if_bt,
                                    bufA, fhi, flo);

    const uint4* fhi4 = (const uint4*)fhi;
    const uint4* flo4 = (const uint4*)flo;
    const uint4* hhi4 = (const uint4*)hhi;
    const uint4* hlo4 = (const uint4*)hlo;

    float* fin = bufA;
    for (int i = 0; i < BB; i++) {
        // temp = feat @ ctr_w[i]
        msg_mma_kernel<false><<<dim3(148, 1), 512, SMEM_BYTES>>>(
            fhi4, flo4, wsp + (size_t)i * 16384, nullptr, nullptr, temp, NN);
        // scatter-add message passes
        msg_mma_kernel<true><<<dim3(74, SS), 512, SMEM_BYTES>>>(
            fhi4, flo4, wsp + (size_t)(6 + i * 6) * 16384, pre_u, pre_v, temp, EE);
        msg_mma_kernel<true><<<dim3(74, SS), 512, SMEM_BYTES>>>(
            fhi4, flo4, wsp + (size_t)(42 + i * 6) * 16384, suc_u, suc_v, temp, EE);
        msg_mma_kernel<true><<<dim3(148, 1), 512, SMEM_BYTES>>>(
            fhi4, flo4, wsp + (size_t)(78 + i) * 16384, left_u, left_v, temp, ELE);
        msg_mma_kernel<true><<<dim3(148, 1), 512, SMEM_BYTES>>>(
            fhi4, flo4, wsp + (size_t)(84 + i) * 16384, right_u, right_v, temp, ELE);
        // h = relu(GN(temp)) -> split planes
        norm_relu_kernel<<<NN / 2, 256>>>(temp, norm_g + i * CC, norm_b + i * CC, hhi, hlo);
        // temp = h @ ctr2_w[i]
        msg_mma_kernel<false><<<dim3(148, 1), 512, SMEM_BYTES>>>(
            hhi4, hlo4, wsp + (size_t)(90 + i) * 16384, nullptr, nullptr, temp, NN);
        // feat = relu(GN(temp) + identity)
        float* dst = (i == BB - 1) ? (float*)d_out : ((fin == bufA) ? bufB : bufA);
        norm_res_kernel<<<NN / 2, 256>>>(temp, ctr2_g + i * CC, ctr2_b + i * CC, fin, dst, fhi, flo);
        fin = dst;
    }
}